// round 2
// baseline (speedup 1.0000x reference)
#include <cuda_runtime.h>
#include <cuda_bf16.h>

// Problem constants (from reference): N=50000, DIM=64, HEADS=4, E=800000.
#define MAXN 50000
#define MAXE 800000
#define MAXET (MAXE + MAXN)
#define HC 256   // HEADS * DIM

// ---------------- scratch (static device globals; no allocation) ----------------
__device__ __align__(16) float g_x[MAXN * HC];        // [N, H, C] = x @ W
__device__ __align__(16) float g_asrc[MAXN * 4];      // [N, H]
__device__ __align__(16) float g_adst[MAXN * 4];      // [N, H]
__device__ float4 g_ex[MAXET];                        // exp(leakyrelu(logits)) per edge
__device__ __align__(16) float g_segsum[MAXN * 4];    // [N, H]
__device__ int   g_deg[MAXN];
__device__ int   g_off[MAXN + 1];
__device__ int   g_cursor[MAXN];
__device__ int   g_srcs[MAXET];                       // CSR-sorted src index
__device__ float4 g_alpha[MAXET];                     // CSR-sorted alpha (pre-scaled by 1/H)
__device__ int   g_src[MAXET];                        // decoded edge src (+ self loops)
__device__ int   g_dst[MAXET];                        // decoded edge dst (+ self loops)
__device__ int   g_is64;                              // 1 if edge buffer is int64

// ---------------- K-1: detect int32 vs int64 edge buffer ----------------
// int64 values < 2^31 have zero high words; random int32 edges make odd words
// nonzero with overwhelming probability over 2048 samples.
__global__ void detect_kernel(const int* __restrict__ e32) {
    __shared__ int s_any;
    if (threadIdx.x == 0) s_any = 0;
    __syncthreads();
    int any = 0;
    for (int i = threadIdx.x; i < 2048; i += blockDim.x)
        any |= e32[2 * i + 1];
    if (any) atomicOr(&s_any, 1);
    __syncthreads();
    if (threadIdx.x == 0) g_is64 = s_any ? 0 : 1;
}

// ---------------- K0: decode edges (+append self loops) & zero-init ----------------
__global__ void decode_init_kernel(const int* __restrict__ e32, int N, int E) {
    int i = blockIdx.x * blockDim.x + threadIdx.x;
    int ET = E + N;
    if (i < ET) {
        int s, d;
        if (i < E) {
            if (g_is64) { s = e32[2 * i]; d = e32[2 * E + 2 * i]; }
            else        { s = e32[i];     d = e32[E + i]; }
        } else {
            s = d = i - E;
        }
        g_src[i] = s;
        g_dst[i] = d;
    }
    if (i < N * 4) g_segsum[i] = 0.0f;
    if (i < N) { g_deg[i] = 0; g_cursor[i] = 0; }
}

// ---------------- K1: GEMM  g_x[N,256] = X[N,64] @ W[64,256] ----------------
__global__ void gemm_kernel(const float* __restrict__ X, const float* __restrict__ W, int N) {
    __shared__ float sx[64][65];
    __shared__ float sw[64][65];
    int row0 = blockIdx.x * 64;
    int col0 = blockIdx.y * 64;
    int t = threadIdx.x; // 256 threads

    #pragma unroll
    for (int i = t; i < 64 * 64; i += 256) {
        int k = i >> 6, j = i & 63;
        sw[k][j] = W[k * 256 + col0 + j];
    }
    #pragma unroll
    for (int i = t; i < 64 * 64; i += 256) {
        int r = i >> 6, k = i & 63;
        int row = row0 + r;
        sx[r][k] = (row < N) ? X[row * 64 + k] : 0.0f;
    }
    __syncthreads();

    int tx = t & 15, ty = t >> 4;
    int r0 = ty * 4, c0 = tx * 4;
    float acc[4][4] = {};
    #pragma unroll
    for (int k = 0; k < 64; k++) {
        float b0 = sw[k][c0 + 0], b1 = sw[k][c0 + 1];
        float b2 = sw[k][c0 + 2], b3 = sw[k][c0 + 3];
        #pragma unroll
        for (int i = 0; i < 4; i++) {
            float a = sx[r0 + i][k];
            acc[i][0] += a * b0; acc[i][1] += a * b1;
            acc[i][2] += a * b2; acc[i][3] += a * b3;
        }
    }
    #pragma unroll
    for (int i = 0; i < 4; i++) {
        int row = row0 + r0 + i;
        if (row < N) {
            float4 v = make_float4(acc[i][0], acc[i][1], acc[i][2], acc[i][3]);
            *(float4*)&g_x[row * HC + col0 + c0] = v;
        }
    }
}

// ---------------- K2: per-node attention coefficients a_src / a_dst ----------------
__global__ void att_kernel(const float* __restrict__ att_src,
                           const float* __restrict__ att_dst, int N) {
    int gw = (blockIdx.x * blockDim.x + threadIdx.x) >> 5;
    int lane = threadIdx.x & 31;
    if (gw >= N) return;
    const float4* yrow = (const float4*)(g_x + gw * HC);
    float4 v0 = yrow[lane * 2], v1 = yrow[lane * 2 + 1];
    const float4* as4 = (const float4*)att_src;
    const float4* ad4 = (const float4*)att_dst;
    float4 s0 = as4[lane * 2], s1 = as4[lane * 2 + 1];
    float4 d0 = ad4[lane * 2], d1 = ad4[lane * 2 + 1];
    float ps = v0.x * s0.x + v0.y * s0.y + v0.z * s0.z + v0.w * s0.w
             + v1.x * s1.x + v1.y * s1.y + v1.z * s1.z + v1.w * s1.w;
    float pd = v0.x * d0.x + v0.y * d0.y + v0.z * d0.z + v0.w * d0.w
             + v1.x * d1.x + v1.y * d1.y + v1.z * d1.z + v1.w * d1.w;
    #pragma unroll
    for (int off = 4; off > 0; off >>= 1) {
        ps += __shfl_down_sync(0xffffffffu, ps, off, 8);
        pd += __shfl_down_sync(0xffffffffu, pd, off, 8);
    }
    if ((lane & 7) == 0) {
        int h = lane >> 3;
        g_asrc[gw * 4 + h] = ps;
        g_adst[gw * 4 + h] = pd;
    }
}

// ---------------- K3: edge pass 1 — exp(leakyrelu(logit)), seg_sum, degree ----------------
__global__ void edge_pass1(int N, int E) {
    int e = blockIdx.x * blockDim.x + threadIdx.x;
    int ET = E + N;
    if (e >= ET) return;
    int s = g_src[e], d = g_dst[e];
    float4 as = *(const float4*)&g_asrc[s * 4];
    float4 ad = *(const float4*)&g_adst[d * 4];
    float l0 = as.x + ad.x, l1 = as.y + ad.y, l2 = as.z + ad.z, l3 = as.w + ad.w;
    l0 = l0 > 0.f ? l0 : 0.2f * l0;
    l1 = l1 > 0.f ? l1 : 0.2f * l1;
    l2 = l2 > 0.f ? l2 : 0.2f * l2;
    l3 = l3 > 0.f ? l3 : 0.2f * l3;
    float4 ex = make_float4(__expf(l0), __expf(l1), __expf(l2), __expf(l3));
    g_ex[e] = ex;
    atomicAdd(&g_segsum[d * 4 + 0], ex.x);
    atomicAdd(&g_segsum[d * 4 + 1], ex.y);
    atomicAdd(&g_segsum[d * 4 + 2], ex.z);
    atomicAdd(&g_segsum[d * 4 + 3], ex.w);
    atomicAdd(&g_deg[d], 1);
}

// ---------------- K4: single-block exclusive scan of degrees -> offsets ----------------
__global__ void scan_kernel(int N) {
    __shared__ int warp_sums[32];
    __shared__ int s_carry;
    int t = threadIdx.x;            // 1024
    int lane = t & 31, wid = t >> 5;
    if (t == 0) s_carry = 0;
    __syncthreads();
    for (int base = 0; base < N; base += 1024) {
        int i = base + t;
        int v = (i < N) ? g_deg[i] : 0;
        int x = v;
        #pragma unroll
        for (int o = 1; o < 32; o <<= 1) {
            int y = __shfl_up_sync(0xffffffffu, x, o);
            if (lane >= o) x += y;
        }
        if (lane == 31) warp_sums[wid] = x;
        __syncthreads();
        if (wid == 0) {
            int w = warp_sums[lane];
            #pragma unroll
            for (int o = 1; o < 32; o <<= 1) {
                int y = __shfl_up_sync(0xffffffffu, w, o);
                if (lane >= o) w += y;
            }
            warp_sums[lane] = w;
        }
        __syncthreads();
        int warp_off = wid ? warp_sums[wid - 1] : 0;
        if (i < N) g_off[i] = s_carry + warp_off + x - v;
        __syncthreads();
        if (t == 0) s_carry += warp_sums[31];
        __syncthreads();
    }
    if (t == 0) g_off[N] = s_carry;
}

// ---------------- K5: edge pass 2 — compute alpha, scatter into CSR order ----------------
__global__ void edge_pass2(int N, int E) {
    int e = blockIdx.x * blockDim.x + threadIdx.x;
    int ET = E + N;
    if (e >= ET) return;
    int s = g_src[e], d = g_dst[e];
    float4 ex = g_ex[e];
    float4 ss = *(const float4*)&g_segsum[d * 4];
    float4 al;
    al.x = 0.25f * ex.x / (ss.x + 1e-16f);
    al.y = 0.25f * ex.y / (ss.y + 1e-16f);
    al.z = 0.25f * ex.z / (ss.z + 1e-16f);
    al.w = 0.25f * ex.w / (ss.w + 1e-16f);
    int pos = g_off[d] + atomicAdd(&g_cursor[d], 1);
    g_srcs[pos] = s;
    g_alpha[pos] = al;
}

// ---------------- K6: warp-per-dst-node aggregation (no float atomics) ----------------
__global__ void aggregate_kernel(const float* __restrict__ bias,
                                 float* __restrict__ out, int N) {
    int gw = (blockIdx.x * blockDim.x + threadIdx.x) >> 5;
    int lane = threadIdx.x & 31;
    if (gw >= N) return;
    int beg = g_off[gw], end = g_off[gw + 1];
    float acc0 = 0.f, acc1 = 0.f;
    for (int j = beg; j < end; j++) {
        int s = g_srcs[j];
        float4 al = g_alpha[j];
        const float* xr = g_x + s * HC;
        acc0 += al.x * xr[lane]       + al.y * xr[64 + lane]
              + al.z * xr[128 + lane] + al.w * xr[192 + lane];
        acc1 += al.x * xr[32 + lane]  + al.y * xr[96 + lane]
              + al.z * xr[160 + lane] + al.w * xr[224 + lane];
    }
    out[gw * 64 + lane]      = acc0 + bias[lane];
    out[gw * 64 + 32 + lane] = acc1 + bias[32 + lane];
}

// ---------------- launch ----------------
extern "C" void kernel_launch(void* const* d_in, const int* in_sizes, int n_in,
                              void* d_out, int out_size) {
    const float* meta_x  = (const float*)d_in[0];
    const int*   edge32  = (const int*)d_in[1];
    const float* W       = (const float*)d_in[2];
    const float* att_src = (const float*)d_in[3];
    const float* att_dst = (const float*)d_in[4];
    const float* bias    = (const float*)d_in[5];
    float*       out     = (float*)d_out;

    int N  = in_sizes[0] / 64;
    int E  = in_sizes[1] / 2;
    int ET = E + N;

    detect_kernel<<<1, 256>>>(edge32);
    decode_init_kernel<<<(ET + 255) / 256, 256>>>(edge32, N, E);
    gemm_kernel<<<dim3((N + 63) / 64, 4), 256>>>(meta_x, W, N);
    att_kernel<<<(N * 32 + 255) / 256, 256>>>(att_src, att_dst, N);
    edge_pass1<<<(ET + 255) / 256, 256>>>(N, E);
    scan_kernel<<<1, 1024>>>(N);
    edge_pass2<<<(ET + 255) / 256, 256>>>(N, E);
    aggregate_kernel<<<(N * 32 + 255) / 256, 256>>>(bias, out, N);
}

// round 3
// speedup vs baseline: 1.3415x; 1.3415x over previous
#include <cuda_runtime.h>
#include <cuda_fp16.h>

// Problem constants (from reference): N=50000, DIM=64, HEADS=4, E=800000.
#define MAXN 50000
#define MAXE 800000
#define MAXET (MAXE + MAXN)
#define HC 256   // HEADS * DIM

// ---------------- scratch (static device globals; no allocation) ----------------
__device__ __align__(16) __half g_xh[MAXN * HC];      // [N, H, C] = x @ W  (fp16)
__device__ __align__(16) float g_asrc[MAXN * 4];      // [N, H]
__device__ __align__(16) float g_adst[MAXN * 4];      // [N, H]
__device__ __align__(16) float g_segsum[MAXN * 4];    // [N, H] sum of exp per dst
__device__ int    g_deg[MAXN];
__device__ int    g_off[MAXN + 1];
__device__ int    g_bsum[64];
__device__ int    g_boff[64];
__device__ int    g_cursor[MAXN];
__device__ int    g_srcs[MAXET];                      // CSR-ordered src index
__device__ float4 g_exv[MAXET];                       // CSR-ordered exp(logits) (unnormalized)
__device__ int    g_src[MAXET];                       // decoded edge src (+ self loops)
__device__ int    g_dst[MAXET];                       // decoded edge dst (+ self loops)
__device__ int    g_is64;                             // 1 if edge buffer is int64

// ---------------- detect int32 vs int64 edge buffer ----------------
__global__ void detect_kernel(const int* __restrict__ e32) {
    __shared__ int s_any;
    if (threadIdx.x == 0) s_any = 0;
    __syncthreads();
    int any = 0;
    for (int i = threadIdx.x; i < 2048; i += blockDim.x)
        any |= e32[2 * i + 1];
    if (any) atomicOr(&s_any, 1);
    __syncthreads();
    if (threadIdx.x == 0) g_is64 = s_any ? 0 : 1;
}

// ---------------- init accumulators ----------------
__global__ void init_kernel(int N) {
    int i = blockIdx.x * blockDim.x + threadIdx.x;
    if (i < N * 4) g_segsum[i] = 0.0f;
    if (i < N) { g_deg[i] = 0; g_cursor[i] = 0; }
}

// ---------------- GEMM g_xh[N,256] = X[N,64] @ W[64,256]  + fused a_src/a_dst ----------------
// blockIdx.y = head; each block owns full 64-col head segment for 64 rows, so the
// per-row attention dot products complete inside the block.
__global__ void gemm_kernel(const float* __restrict__ X, const float* __restrict__ W,
                            const float* __restrict__ att_src,
                            const float* __restrict__ att_dst, int N) {
    __shared__ float sx[64][65];
    __shared__ float sw[64][65];
    int row0 = blockIdx.x * 64;
    int hy   = blockIdx.y;          // head
    int col0 = hy * 64;
    int t = threadIdx.x;            // 256 threads

    #pragma unroll
    for (int i = t; i < 64 * 64; i += 256) {
        int k = i >> 6, j = i & 63;
        sw[k][j] = W[k * 256 + col0 + j];
    }
    #pragma unroll
    for (int i = t; i < 64 * 64; i += 256) {
        int r = i >> 6, k = i & 63;
        int row = row0 + r;
        sx[r][k] = (row < N) ? X[row * 64 + k] : 0.0f;
    }
    __syncthreads();

    int tx = t & 15, ty = t >> 4;
    int r0 = ty * 4, c0 = tx * 4;
    float acc[4][4] = {};
    #pragma unroll
    for (int k = 0; k < 64; k++) {
        float b0 = sw[k][c0 + 0], b1 = sw[k][c0 + 1];
        float b2 = sw[k][c0 + 2], b3 = sw[k][c0 + 3];
        #pragma unroll
        for (int i = 0; i < 4; i++) {
            float a = sx[r0 + i][k];
            acc[i][0] += a * b0; acc[i][1] += a * b1;
            acc[i][2] += a * b2; acc[i][3] += a * b3;
        }
    }

    // store fp16 features
    #pragma unroll
    for (int i = 0; i < 4; i++) {
        int row = row0 + r0 + i;
        if (row < N) {
            __half2 h01 = __floats2half2_rn(acc[i][0], acc[i][1]);
            __half2 h23 = __floats2half2_rn(acc[i][2], acc[i][3]);
            __half2* dst = (__half2*)&g_xh[row * HC + col0 + c0];
            dst[0] = h01; dst[1] = h23;
        }
    }

    // fused attention coefficients: a = sum_c x[row,c]*att[h,c]
    float4 as = *(const float4*)&att_src[col0 + c0];
    float4 ad = *(const float4*)&att_dst[col0 + c0];
    #pragma unroll
    for (int i = 0; i < 4; i++) {
        float ps = acc[i][0] * as.x + acc[i][1] * as.y + acc[i][2] * as.z + acc[i][3] * as.w;
        float pd = acc[i][0] * ad.x + acc[i][1] * ad.y + acc[i][2] * ad.z + acc[i][3] * ad.w;
        #pragma unroll
        for (int off = 8; off > 0; off >>= 1) {
            ps += __shfl_down_sync(0xffffffffu, ps, off, 16);
            pd += __shfl_down_sync(0xffffffffu, pd, off, 16);
        }
        if (tx == 0) {
            int row = row0 + r0 + i;
            if (row < N) {
                g_asrc[row * 4 + hy] = ps;
                g_adst[row * 4 + hy] = pd;
            }
        }
    }
}

// ---------------- edge pass 1 (fused decode): ex -> segsum, degree ----------------
__global__ void edge_pass1(const int* __restrict__ e32, int N, int E) {
    int e = blockIdx.x * blockDim.x + threadIdx.x;
    int ET = E + N;
    if (e >= ET) return;
    int s, d;
    if (e < E) {
        if (g_is64) { s = e32[2 * e]; d = e32[2 * E + 2 * e]; }
        else        { s = e32[e];     d = e32[E + e]; }
    } else {
        s = d = e - E;
    }
    g_src[e] = s;
    g_dst[e] = d;
    float4 as = *(const float4*)&g_asrc[s * 4];
    float4 ad = *(const float4*)&g_adst[d * 4];
    float l0 = as.x + ad.x, l1 = as.y + ad.y, l2 = as.z + ad.z, l3 = as.w + ad.w;
    l0 = l0 > 0.f ? l0 : 0.2f * l0;
    l1 = l1 > 0.f ? l1 : 0.2f * l1;
    l2 = l2 > 0.f ? l2 : 0.2f * l2;
    l3 = l3 > 0.f ? l3 : 0.2f * l3;
    atomicAdd(&g_segsum[d * 4 + 0], __expf(l0));
    atomicAdd(&g_segsum[d * 4 + 1], __expf(l1));
    atomicAdd(&g_segsum[d * 4 + 2], __expf(l2));
    atomicAdd(&g_segsum[d * 4 + 3], __expf(l3));
    atomicAdd(&g_deg[d], 1);
}

// ---------------- 3-kernel scan: deg -> exclusive offsets ----------------
__global__ void scan_local(int N) {     // grid: ceil(N/1024), block 1024
    __shared__ int wsum[32];
    int t = threadIdx.x, lane = t & 31, wid = t >> 5;
    int i = blockIdx.x * 1024 + t;
    int v = (i < N) ? g_deg[i] : 0;
    int x = v;
    #pragma unroll
    for (int o = 1; o < 32; o <<= 1) {
        int y = __shfl_up_sync(0xffffffffu, x, o);
        if (lane >= o) x += y;
    }
    if (lane == 31) wsum[wid] = x;
    __syncthreads();
    if (wid == 0) {
        int w = wsum[lane];
        #pragma unroll
        for (int o = 1; o < 32; o <<= 1) {
            int y = __shfl_up_sync(0xffffffffu, w, o);
            if (lane >= o) w += y;
        }
        wsum[lane] = w;
    }
    __syncthreads();
    int ex = (wid ? wsum[wid - 1] : 0) + x - v;
    if (i < N) g_off[i] = ex;
    if (t == 1023) g_bsum[blockIdx.x] = wsum[31];
}

__global__ void scan_blocks(int nb) {   // 1 block, 64 threads
    int t = threadIdx.x, lane = t & 31, wid = t >> 5;
    __shared__ int w0tot;
    int v = (t < nb) ? g_bsum[t] : 0;
    int x = v;
    #pragma unroll
    for (int o = 1; o < 32; o <<= 1) {
        int y = __shfl_up_sync(0xffffffffu, x, o);
        if (lane >= o) x += y;
    }
    if (wid == 0 && lane == 31) w0tot = x;
    __syncthreads();
    int ex = x - v + (wid ? w0tot : 0);
    if (t < nb) g_boff[t] = ex;
}

__global__ void scan_add(int N, int ET) {
    int i = blockIdx.x * 1024 + threadIdx.x;
    if (i < N) g_off[i] += g_boff[blockIdx.x];
    if (i == 0) g_off[N] = ET;
}

// ---------------- edge pass 2: recompute ex, scatter into CSR order ----------------
__global__ void edge_pass2(int N, int E) {
    int e = blockIdx.x * blockDim.x + threadIdx.x;
    int ET = E + N;
    if (e >= ET) return;
    int s = g_src[e], d = g_dst[e];
    float4 as = *(const float4*)&g_asrc[s * 4];
    float4 ad = *(const float4*)&g_adst[d * 4];
    float l0 = as.x + ad.x, l1 = as.y + ad.y, l2 = as.z + ad.z, l3 = as.w + ad.w;
    l0 = l0 > 0.f ? l0 : 0.2f * l0;
    l1 = l1 > 0.f ? l1 : 0.2f * l1;
    l2 = l2 > 0.f ? l2 : 0.2f * l2;
    l3 = l3 > 0.f ? l3 : 0.2f * l3;
    float4 ex = make_float4(__expf(l0), __expf(l1), __expf(l2), __expf(l3));
    int pos = g_off[d] + atomicAdd(&g_cursor[d], 1);
    g_srcs[pos] = s;
    g_exv[pos] = ex;
}

// ---------------- warp-per-dst-node aggregation (fp16 gather, fp32 accum) ----------------
__global__ void aggregate_kernel(const float* __restrict__ bias,
                                 float* __restrict__ out, int N) {
    int gw = (blockIdx.x * blockDim.x + threadIdx.x) >> 5;
    int lane = threadIdx.x & 31;
    if (gw >= N) return;
    int beg = g_off[gw], end = g_off[gw + 1];
    float a00 = 0.f, a01 = 0.f, a10 = 0.f, a11 = 0.f;
    float a20 = 0.f, a21 = 0.f, a30 = 0.f, a31 = 0.f;
    for (int j = beg; j < end; j++) {
        int s = g_srcs[j];
        float4 w = g_exv[j];
        const __half2* xr = (const __half2*)(g_xh + s * HC);
        float2 v0 = __half22float2(xr[lane]);
        float2 v1 = __half22float2(xr[32 + lane]);
        float2 v2 = __half22float2(xr[64 + lane]);
        float2 v3 = __half22float2(xr[96 + lane]);
        a00 += w.x * v0.x; a01 += w.x * v0.y;
        a10 += w.y * v1.x; a11 += w.y * v1.y;
        a20 += w.z * v2.x; a21 += w.z * v2.y;
        a30 += w.w * v3.x; a31 += w.w * v3.y;
    }
    float4 ss = *(const float4*)&g_segsum[gw * 4];
    float n0 = 0.25f / (ss.x + 1e-16f);
    float n1 = 0.25f / (ss.y + 1e-16f);
    float n2 = 0.25f / (ss.z + 1e-16f);
    float n3 = 0.25f / (ss.w + 1e-16f);
    int c = 2 * lane;
    float o0 = a00 * n0 + a10 * n1 + a20 * n2 + a30 * n3 + bias[c];
    float o1 = a01 * n0 + a11 * n1 + a21 * n2 + a31 * n3 + bias[c + 1];
    *(float2*)&out[gw * 64 + c] = make_float2(o0, o1);
}

// ---------------- launch ----------------
extern "C" void kernel_launch(void* const* d_in, const int* in_sizes, int n_in,
                              void* d_out, int out_size) {
    const float* meta_x  = (const float*)d_in[0];
    const int*   edge32  = (const int*)d_in[1];
    const float* W       = (const float*)d_in[2];
    const float* att_src = (const float*)d_in[3];
    const float* att_dst = (const float*)d_in[4];
    const float* bias    = (const float*)d_in[5];
    float*       out     = (float*)d_out;

    int N  = in_sizes[0] / 64;
    int E  = in_sizes[1] / 2;
    int ET = E + N;
    int nb = (N + 1023) / 1024;

    detect_kernel<<<1, 256>>>(edge32);
    init_kernel<<<(N * 4 + 255) / 256, 256>>>(N);
    gemm_kernel<<<dim3((N + 63) / 64, 4), 256>>>(meta_x, W, att_src, att_dst, N);
    edge_pass1<<<(ET + 255) / 256, 256>>>(edge32, N, E);
    scan_local<<<nb, 1024>>>(N);
    scan_blocks<<<1, 64>>>(nb);
    scan_add<<<nb, 1024>>>(N, ET);
    edge_pass2<<<(ET + 255) / 256, 256>>>(N, E);
    aggregate_kernel<<<(N * 32 + 255) / 256, 256>>>(bias, out, N);
}

// round 4
// speedup vs baseline: 1.5790x; 1.1770x over previous
#include <cuda_runtime.h>
#include <cuda_fp16.h>

// Problem constants (from reference): N=50000, DIM=64, HEADS=4, E=800000.
#define MAXN 50000
#define MAXE 800000
#define MAXET (MAXE + MAXN)
#define HC 256   // HEADS * DIM

// ---------------- scratch (static device globals; no allocation) ----------------
__device__ __align__(16) __half g_xh[MAXN * HC];      // [N, H, C] = x @ W  (fp16)
__device__ __align__(16) float g_asrc[MAXN * 4];      // [N, H]
__device__ __align__(16) float g_adst[MAXN * 4];      // [N, H]
__device__ int    g_deg[MAXN];
__device__ int    g_off[MAXN + 1];
__device__ int    g_bsum[64];
__device__ int    g_boff[64];
__device__ int    g_cursor[MAXN];
__device__ int    g_srcs[MAXET];                      // CSR-ordered src index
__device__ float4 g_exv[MAXET];                       // CSR-ordered exp(logits) (unnormalized)
__device__ int    g_is64;                             // 1 if edge buffer is int64

// ---------------- detect int32 vs int64 edge buffer ----------------
__global__ void detect_kernel(const int* __restrict__ e32) {
    __shared__ int s_any;
    if (threadIdx.x == 0) s_any = 0;
    __syncthreads();
    int any = 0;
    for (int i = threadIdx.x; i < 2048; i += blockDim.x)
        any |= e32[2 * i + 1];
    if (any) atomicOr(&s_any, 1);
    __syncthreads();
    if (threadIdx.x == 0) g_is64 = s_any ? 0 : 1;
}

// ---------------- init counters ----------------
__global__ void init_kernel(int N) {
    int i = blockIdx.x * blockDim.x + threadIdx.x;
    if (i < N) { g_deg[i] = 0; g_cursor[i] = 0; }
}

// ---------------- GEMM g_xh[N,256] = X[N,64] @ W[64,256]  + fused a_src/a_dst ----------------
__global__ void gemm_kernel(const float* __restrict__ X, const float* __restrict__ W,
                            const float* __restrict__ att_src,
                            const float* __restrict__ att_dst, int N) {
    __shared__ float sx[64][65];
    __shared__ float sw[64][65];
    int row0 = blockIdx.x * 64;
    int hy   = blockIdx.y;          // head
    int col0 = hy * 64;
    int t = threadIdx.x;            // 256 threads

    #pragma unroll
    for (int i = t; i < 64 * 64; i += 256) {
        int k = i >> 6, j = i & 63;
        sw[k][j] = W[k * 256 + col0 + j];
    }
    #pragma unroll
    for (int i = t; i < 64 * 64; i += 256) {
        int r = i >> 6, k = i & 63;
        int row = row0 + r;
        sx[r][k] = (row < N) ? X[row * 64 + k] : 0.0f;
    }
    __syncthreads();

    int tx = t & 15, ty = t >> 4;
    int r0 = ty * 4, c0 = tx * 4;
    float acc[4][4] = {};
    #pragma unroll
    for (int k = 0; k < 64; k++) {
        float b0 = sw[k][c0 + 0], b1 = sw[k][c0 + 1];
        float b2 = sw[k][c0 + 2], b3 = sw[k][c0 + 3];
        #pragma unroll
        for (int i = 0; i < 4; i++) {
            float a = sx[r0 + i][k];
            acc[i][0] += a * b0; acc[i][1] += a * b1;
            acc[i][2] += a * b2; acc[i][3] += a * b3;
        }
    }

    // store fp16 features
    #pragma unroll
    for (int i = 0; i < 4; i++) {
        int row = row0 + r0 + i;
        if (row < N) {
            __half2 h01 = __floats2half2_rn(acc[i][0], acc[i][1]);
            __half2 h23 = __floats2half2_rn(acc[i][2], acc[i][3]);
            __half2* dst = (__half2*)&g_xh[row * HC + col0 + c0];
            dst[0] = h01; dst[1] = h23;
        }
    }

    // fused attention coefficients: a = sum_c x[row,c]*att[h,c]
    float4 as = *(const float4*)&att_src[col0 + c0];
    float4 ad = *(const float4*)&att_dst[col0 + c0];
    #pragma unroll
    for (int i = 0; i < 4; i++) {
        float ps = acc[i][0] * as.x + acc[i][1] * as.y + acc[i][2] * as.z + acc[i][3] * as.w;
        float pd = acc[i][0] * ad.x + acc[i][1] * ad.y + acc[i][2] * ad.z + acc[i][3] * ad.w;
        #pragma unroll
        for (int off = 8; off > 0; off >>= 1) {
            ps += __shfl_down_sync(0xffffffffu, ps, off, 16);
            pd += __shfl_down_sync(0xffffffffu, pd, off, 16);
        }
        if (tx == 0) {
            int row = row0 + r0 + i;
            if (row < N) {
                g_asrc[row * 4 + hy] = ps;
                g_adst[row * 4 + hy] = pd;
            }
        }
    }
}

// ---------------- degree histogram (decode dst only) ----------------
__global__ void degree_kernel(const int* __restrict__ e32, int N, int E) {
    int e = blockIdx.x * blockDim.x + threadIdx.x;
    int ET = E + N;
    if (e >= ET) return;
    int d;
    if (e < E) d = g_is64 ? e32[2 * E + 2 * e] : e32[E + e];
    else       d = e - E;
    atomicAdd(&g_deg[d], 1);
}

// ---------------- 3-kernel scan: deg -> exclusive offsets ----------------
__global__ void scan_local(int N) {     // grid: ceil(N/1024), block 1024
    __shared__ int wsum[32];
    int t = threadIdx.x, lane = t & 31, wid = t >> 5;
    int i = blockIdx.x * 1024 + t;
    int v = (i < N) ? g_deg[i] : 0;
    int x = v;
    #pragma unroll
    for (int o = 1; o < 32; o <<= 1) {
        int y = __shfl_up_sync(0xffffffffu, x, o);
        if (lane >= o) x += y;
    }
    if (lane == 31) wsum[wid] = x;
    __syncthreads();
    if (wid == 0) {
        int w = wsum[lane];
        #pragma unroll
        for (int o = 1; o < 32; o <<= 1) {
            int y = __shfl_up_sync(0xffffffffu, w, o);
            if (lane >= o) w += y;
        }
        wsum[lane] = w;
    }
    __syncthreads();
    int ex = (wid ? wsum[wid - 1] : 0) + x - v;
    if (i < N) g_off[i] = ex;
    if (t == 1023) g_bsum[blockIdx.x] = wsum[31];
}

__global__ void scan_blocks(int nb) {   // 1 block, 64 threads
    int t = threadIdx.x, lane = t & 31, wid = t >> 5;
    __shared__ int w0tot;
    int v = (t < nb) ? g_bsum[t] : 0;
    int x = v;
    #pragma unroll
    for (int o = 1; o < 32; o <<= 1) {
        int y = __shfl_up_sync(0xffffffffu, x, o);
        if (lane >= o) x += y;
    }
    if (wid == 0 && lane == 31) w0tot = x;
    __syncthreads();
    int ex = x - v + (wid ? w0tot : 0);
    if (t < nb) g_boff[t] = ex;
}

__global__ void scan_add(int N, int ET) {
    int i = blockIdx.x * 1024 + threadIdx.x;
    if (i < N) g_off[i] += g_boff[blockIdx.x];
    if (i == 0) g_off[N] = ET;
}

// ---------------- edge pass 2: decode, exp(leakyrelu), scatter into CSR order ----------------
__global__ void edge_pass2(const int* __restrict__ e32, int N, int E) {
    int e = blockIdx.x * blockDim.x + threadIdx.x;
    int ET = E + N;
    if (e >= ET) return;
    int s, d;
    if (e < E) {
        if (g_is64) { s = e32[2 * e]; d = e32[2 * E + 2 * e]; }
        else        { s = e32[e];     d = e32[E + e]; }
    } else {
        s = d = e - E;
    }
    float4 as = *(const float4*)&g_asrc[s * 4];
    float4 ad = *(const float4*)&g_adst[d * 4];
    float l0 = as.x + ad.x, l1 = as.y + ad.y, l2 = as.z + ad.z, l3 = as.w + ad.w;
    l0 = l0 > 0.f ? l0 : 0.2f * l0;
    l1 = l1 > 0.f ? l1 : 0.2f * l1;
    l2 = l2 > 0.f ? l2 : 0.2f * l2;
    l3 = l3 > 0.f ? l3 : 0.2f * l3;
    float4 ex = make_float4(__expf(l0), __expf(l1), __expf(l2), __expf(l3));
    int pos = g_off[d] + atomicAdd(&g_cursor[d], 1);
    g_srcs[pos] = s;
    g_exv[pos] = ex;
}

// ---------------- warp-per-dst-node aggregation; segsum computed in-loop ----------------
__global__ void aggregate_kernel(const float* __restrict__ bias,
                                 float* __restrict__ out, int N) {
    int gw = (blockIdx.x * blockDim.x + threadIdx.x) >> 5;
    int lane = threadIdx.x & 31;
    if (gw >= N) return;
    int beg = g_off[gw], end = g_off[gw + 1];
    float a00 = 0.f, a01 = 0.f, a10 = 0.f, a11 = 0.f;
    float a20 = 0.f, a21 = 0.f, a30 = 0.f, a31 = 0.f;
    float s0 = 0.f, s1 = 0.f, s2 = 0.f, s3 = 0.f;
    for (int j = beg; j < end; j++) {
        int s = g_srcs[j];
        float4 w = g_exv[j];
        const __half2* xr = (const __half2*)(g_xh + s * HC);
        float2 v0 = __half22float2(xr[lane]);
        float2 v1 = __half22float2(xr[32 + lane]);
        float2 v2 = __half22float2(xr[64 + lane]);
        float2 v3 = __half22float2(xr[96 + lane]);
        a00 += w.x * v0.x; a01 += w.x * v0.y;
        a10 += w.y * v1.x; a11 += w.y * v1.y;
        a20 += w.z * v2.x; a21 += w.z * v2.y;
        a30 += w.w * v3.x; a31 += w.w * v3.y;
        s0 += w.x; s1 += w.y; s2 += w.z; s3 += w.w;
    }
    float n0 = 0.25f / (s0 + 1e-16f);
    float n1 = 0.25f / (s1 + 1e-16f);
    float n2 = 0.25f / (s2 + 1e-16f);
    float n3 = 0.25f / (s3 + 1e-16f);
    int c = 2 * lane;
    float o0 = a00 * n0 + a10 * n1 + a20 * n2 + a30 * n3 + bias[c];
    float o1 = a01 * n0 + a11 * n1 + a21 * n2 + a31 * n3 + bias[c + 1];
    *(float2*)&out[gw * 64 + c] = make_float2(o0, o1);
}

// ---------------- launch ----------------
extern "C" void kernel_launch(void* const* d_in, const int* in_sizes, int n_in,
                              void* d_out, int out_size) {
    const float* meta_x  = (const float*)d_in[0];
    const int*   edge32  = (const int*)d_in[1];
    const float* W       = (const float*)d_in[2];
    const float* att_src = (const float*)d_in[3];
    const float* att_dst = (const float*)d_in[4];
    const float* bias    = (const float*)d_in[5];
    float*       out     = (float*)d_out;

    int N  = in_sizes[0] / 64;
    int E  = in_sizes[1] / 2;
    int ET = E + N;
    int nb = (N + 1023) / 1024;

    detect_kernel<<<1, 256>>>(edge32);
    init_kernel<<<(N + 255) / 256, 256>>>(N);
    gemm_kernel<<<dim3((N + 63) / 64, 4), 256>>>(meta_x, W, att_src, att_dst, N);
    degree_kernel<<<(ET + 255) / 256, 256>>>(edge32, N, E);
    scan_local<<<nb, 1024>>>(N);
    scan_blocks<<<1, 64>>>(nb);
    scan_add<<<nb, 1024>>>(N, ET);
    edge_pass2<<<(ET + 255) / 256, 256>>>(edge32, N, E);
    aggregate_kernel<<<(N * 32 + 255) / 256, 256>>>(bias, out, N);
}